// round 14
// baseline (speedup 1.0000x reference)
#include <cuda_runtime.h>
#include <cuda_bf16.h>
#include <cstdint>

#define B_  4
#define L_  4096
#define D_  768
#define CD_ 2304
#define OD_ 1536
#define EMB_ 33
#define FFN_ 64
#define FREQ_ 10.0f
#define TAPS 32
#define MTOT (B_*L_)        // 16384
#define KSP  768
#define LDA  1536           // 2*KSP (hi|lo)

// ---------------- scratch ------------------------------------------------
__device__ float g_projT[ (size_t)CD_*MTOT ];
__device__ float g_h1   [ TAPS*FFN_ ];
__device__ float g_taps [ 2*D_*TAPS ];
__device__ __nv_bfloat16 g_A1 [(size_t)MTOT*LDA];   // [m][2K]
__device__ __nv_bfloat16 g_B1 [(size_t)CD_*LDA];
__device__ __nv_bfloat16 g_A2T[(size_t)LDA*MTOT];   // [2K][m] K-major
__device__ __nv_bfloat16 g_B2 [(size_t)D_*LDA];

// ---------------- helpers --------------------------------------------------
__device__ __forceinline__ uint32_t smem_u32(const void* p) {
    uint32_t a;
    asm("{ .reg .u64 t; cvta.to.shared.u64 t, %1; cvt.u32.u64 %0, t; }" : "=r"(a) : "l"(p));
    return a;
}
#define SWZ128(o) ((o) ^ (((o) >> 3) & 0x70))

#define LDSM_X4(r0,r1,r2,r3,addr)                                              \
    asm volatile("ldmatrix.sync.aligned.m8n8.x4.shared.b16 {%0,%1,%2,%3}, [%4];" \
        : "=r"(r0), "=r"(r1), "=r"(r2), "=r"(r3) : "r"(addr))

#define LDSM_X4T(r0,r1,r2,r3,addr)                                             \
    asm volatile("ldmatrix.sync.aligned.m8n8.x4.trans.shared.b16 {%0,%1,%2,%3}, [%4];" \
        : "=r"(r0), "=r"(r1), "=r"(r2), "=r"(r3) : "r"(addr))

#define MMA16816(d, a, b0, b1)                                                 \
    asm volatile("mma.sync.aligned.m16n8k16.row.col.f32.bf16.bf16.f32 "        \
        "{%0,%1,%2,%3},{%4,%5,%6,%7},{%8,%9},{%0,%1,%2,%3};"                   \
        : "+f"((d)[0]), "+f"((d)[1]), "+f"((d)[2]), "+f"((d)[3])               \
        : "r"((a)[0]), "r"((a)[1]), "r"((a)[2]), "r"((a)[3]), "r"(b0), "r"(b1))

// 64(M) x 128(N) CTA tile, 128 threads, warp tile 32x64.
// Superchunk stage: A_hi | A_lo | B_hi | B_lo (hi/lo for the SAME 64 k's)
#define GBM 64
#define GBN 128
#define ATILE 8192
#define BTILE 16384
#define STAGEB (2*ATILE + 2*BTILE)   // 49152
#define NSTAGE 2
#define GSMEM (NSTAGE*STAGEB)        // 98304

// quarter-fills: issue 1/4 of a tile's cp.asyncs (part = 0..3)
__device__ __forceinline__ void fill_tileA_part(uint32_t sdst, const __nv_bfloat16* g,
                                                int tid, int part) {
    int idx = tid + (part << 7);
    int row = idx >> 3;
    int c16 = idx & 7;
    uint32_t bo = (uint32_t)(row << 7) + (c16 << 4);
    const void* src = g + (size_t)row * LDA + (c16 << 3);
    asm volatile("cp.async.cg.shared.global [%0], [%1], 16;"
                 :: "r"(sdst + SWZ128(bo)), "l"(src));
}

__device__ __forceinline__ void fill_tileB_part(uint32_t sdst, const __nv_bfloat16* g,
                                                int tid, int part) {
    #pragma unroll
    for (int j = 0; j < 2; j++) {
        int idx = tid + ((part * 2 + j) << 7);
        int row = idx >> 3;
        int c16 = idx & 7;
        uint32_t bo = (uint32_t)(row << 7) + (c16 << 4);
        const void* src = g + (size_t)row * LDA + (c16 << 3);
        asm volatile("cp.async.cg.shared.global [%0], [%1], 16;"
                     :: "r"(sdst + SWZ128(bo)), "l"(src));
    }
}

__device__ __forceinline__ void fill_tile_km_part(uint32_t sdst, const __nv_bfloat16* g,
                                                  int tid, int part) {
    int idx = tid + (part << 7);
    int k  = idx >> 3;
    int mc = idx & 7;
    uint32_t bo = (uint32_t)k * 128 + (((uint32_t)mc << 4) ^ ((k & 7) << 4));
    const void* src = g + (size_t)k * MTOT + (mc << 3);
    asm volatile("cp.async.cg.shared.global [%0], [%1], 16;"
                 :: "r"(sdst + bo), "l"(src));
}

__device__ __forceinline__ void fill_tileA(uint32_t sdst, const __nv_bfloat16* g, int tid) {
    #pragma unroll
    for (int p = 0; p < 4; p++) fill_tileA_part(sdst, g, tid, p);
}
__device__ __forceinline__ void fill_tileB(uint32_t sdst, const __nv_bfloat16* g, int tid) {
    #pragma unroll
    for (int p = 0; p < 4; p++) fill_tileB_part(sdst, g, tid, p);
}
__device__ __forceinline__ void fill_tile_km(uint32_t sdst, const __nv_bfloat16* g, int tid) {
    #pragma unroll
    for (int p = 0; p < 4; p++) fill_tile_km_part(sdst, g, tid, p);
}

// ---------------- GEMM1: A[m][2K] row-major, C_T[n][MTOT] transposed out ----
__global__ void __launch_bounds__(128, 2)
gemm_hmma_kernel(const __nv_bfloat16* __restrict__ A, const __nv_bfloat16* __restrict__ Bm,
                 const float* __restrict__ bias, float* __restrict__ C, int N) {
    extern __shared__ __align__(1024) char smem[];
    uint32_t sb = smem_u32(smem);
    int tid = threadIdx.x;
    int lane = tid & 31;
    int wid = tid >> 5;
    int wm = wid & 1;
    int wn = wid >> 1;
    int m0 = blockIdx.y * GBM;
    int n0 = blockIdx.x * GBN;
    const __nv_bfloat16* Ab = A + (size_t)m0 * LDA;
    const __nv_bfloat16* Bb = Bm + (size_t)n0 * LDA;

    int gid = lane >> 2, tg = lane & 3;
    int arow_l = (lane & 7) + ((lane >> 3) & 1) * 8;
    int acol_l = (lane >> 4) * 16;
    int brow_l = (lane & 7) + (lane >> 4) * 8;
    int bcol_l = ((lane >> 3) & 1) * 16;

    float acc[2][8][4] = {};
    const int kc = KSP / 64;

    {
        uint32_t st = sb;
        fill_tileA(st,             Ab,       tid);
        fill_tileA(st + ATILE,     Ab + KSP, tid);
        fill_tileB(st + 2*ATILE,         Bb,       tid);
        fill_tileB(st + 2*ATILE + BTILE, Bb + KSP, tid);
        asm volatile("cp.async.commit_group;");
    }

    for (int c = 0; c < kc; c++) {
        asm volatile("cp.async.wait_group %0;" :: "n"(0));
        __syncthreads();
        int cn = c + 1;
        bool pf = (cn < kc);
        uint32_t st = sb + (cn & 1) * STAGEB;
        int kk = cn * 64;

        uint32_t sAh = sb + (c & 1) * STAGEB;
        uint32_t sAl = sAh + ATILE;
        uint32_t sBh = sAh + 2*ATILE;
        uint32_t sBl = sBh + BTILE;
        #pragma unroll
        for (int ks = 0; ks < 4; ks++) {
            uint32_t ah[2][4], al[2][4], bh[4][4], bl[4][4];
            // --- half 1: hi fragments + A prefetch, then hi*hi MMAs ---
            #pragma unroll
            for (int mf = 0; mf < 2; mf++) {
                uint32_t off = (uint32_t)(wm * 32 + mf * 16 + arow_l) * 128 + ks * 32 + acol_l;
                LDSM_X4(ah[mf][0], ah[mf][1], ah[mf][2], ah[mf][3], sAh + SWZ128(off));
            }
            #pragma unroll
            for (int nf2 = 0; nf2 < 4; nf2++) {
                uint32_t off = (uint32_t)(wn * 64 + nf2 * 16 + brow_l) * 128 + ks * 32 + bcol_l;
                LDSM_X4(bh[nf2][0], bh[nf2][1], bh[nf2][2], bh[nf2][3], sBh + SWZ128(off));
            }
            if (pf) {
                fill_tileA_part(st,         Ab + kk,       tid, ks);
                fill_tileA_part(st + ATILE, Ab + KSP + kk, tid, ks);
            }
            #pragma unroll
            for (int mf = 0; mf < 2; mf++)
                #pragma unroll
                for (int nf = 0; nf < 8; nf++) {
                    uint32_t* bhp = &bh[nf >> 1][(nf & 1) * 2];
                    MMA16816(acc[mf][nf], ah[mf], bhp[0], bhp[1]);
                }
            // --- half 2: lo fragments + B prefetch, then lo*hi and hi*lo ---
            #pragma unroll
            for (int mf = 0; mf < 2; mf++) {
                uint32_t off = (uint32_t)(wm * 32 + mf * 16 + arow_l) * 128 + ks * 32 + acol_l;
                LDSM_X4(al[mf][0], al[mf][1], al[mf][2], al[mf][3], sAl + SWZ128(off));
            }
            #pragma unroll
            for (int nf2 = 0; nf2 < 4; nf2++) {
                uint32_t off = (uint32_t)(wn * 64 + nf2 * 16 + brow_l) * 128 + ks * 32 + bcol_l;
                LDSM_X4(bl[nf2][0], bl[nf2][1], bl[nf2][2], bl[nf2][3], sBl + SWZ128(off));
            }
            if (pf) {
                fill_tileB_part(st + 2*ATILE,         Bb + kk,       tid, ks);
                fill_tileB_part(st + 2*ATILE + BTILE, Bb + KSP + kk, tid, ks);
            }
            #pragma unroll
            for (int mf = 0; mf < 2; mf++)
                #pragma unroll
                for (int nf = 0; nf < 8; nf++) {
                    uint32_t* bhp = &bh[nf >> 1][(nf & 1) * 2];
                    uint32_t* blp = &bl[nf >> 1][(nf & 1) * 2];
                    MMA16816(acc[mf][nf], al[mf], bhp[0], bhp[1]);
                    MMA16816(acc[mf][nf], ah[mf], blp[0], blp[1]);
                }
        }
        asm volatile("cp.async.commit_group;");
    }

    // transposed epilogue through smem: smt[64][129]
    __syncthreads();
    float* smt = reinterpret_cast<float*>(smem);
    #pragma unroll
    for (int mf = 0; mf < 2; mf++) {
        int mr = wm * 32 + mf * 16 + gid;
        #pragma unroll
        for (int nf = 0; nf < 8; nf++) {
            int nr = wn * 64 + nf * 8 + tg * 2;
            smt[mr * 129 + nr]           = acc[mf][nf][0];
            smt[mr * 129 + nr + 1]       = acc[mf][nf][1];
            smt[(mr + 8) * 129 + nr]     = acc[mf][nf][2];
            smt[(mr + 8) * 129 + nr + 1] = acc[mf][nf][3];
        }
    }
    __syncthreads();
    int nl = tid >> 4;
    int ms = (tid & 15) * 4;
    #pragma unroll
    for (int it = 0; it < 16; it++) {
        int n = it * 8 + nl;
        float bn = bias[n0 + n];
        float4 v;
        v.x = smt[(ms + 0) * 129 + n] + bn;
        v.y = smt[(ms + 1) * 129 + n] + bn;
        v.z = smt[(ms + 2) * 129 + n] + bn;
        v.w = smt[(ms + 3) * 129 + n] + bn;
        *reinterpret_cast<float4*>(C + (size_t)(n0 + n) * MTOT + m0 + ms) = v;
    }
}

// ---------------- GEMM2: A K-major A2T[2K][MTOT], C[m][n] row-major ---------
__global__ void __launch_bounds__(128, 2)
gemm2_hmma_kernel(const __nv_bfloat16* __restrict__ AT, const __nv_bfloat16* __restrict__ Bm,
                  const float* __restrict__ bias, float* __restrict__ C, int N) {
    extern __shared__ __align__(1024) char smem[];
    uint32_t sb = smem_u32(smem);
    int tid = threadIdx.x;
    int lane = tid & 31;
    int wid = tid >> 5;
    int wm = wid & 1;
    int wn = wid >> 1;
    int m0 = blockIdx.y * GBM;
    int n0 = blockIdx.x * GBN;
    const __nv_bfloat16* Ab = AT + m0;
    const __nv_bfloat16* Bb = Bm + (size_t)n0 * LDA;

    int gid = lane >> 2, tg = lane & 3;
    float2 br[8];
    #pragma unroll
    for (int nf = 0; nf < 8; nf++) {
        int n = n0 + wn * 64 + nf * 8 + tg * 2;
        br[nf] = *reinterpret_cast<const float2*>(bias + n);
    }

    int krow_l = (lane & 7) + ((lane >> 4) & 1) * 8;
    int mcol_l = ((lane >> 3) & 1) * 8;
    int brow_l = (lane & 7) + (lane >> 4) * 8;
    int bcol_l = ((lane >> 3) & 1) * 16;

    float acc[2][8][4] = {};
    const int kc = KSP / 64;

    {
        uint32_t st = sb;
        fill_tile_km(st,         Ab,                      tid);
        fill_tile_km(st + ATILE, Ab + (size_t)KSP * MTOT, tid);
        fill_tileB(st + 2*ATILE,         Bb,       tid);
        fill_tileB(st + 2*ATILE + BTILE, Bb + KSP, tid);
        asm volatile("cp.async.commit_group;");
    }

    for (int c = 0; c < kc; c++) {
        asm volatile("cp.async.wait_group %0;" :: "n"(0));
        __syncthreads();
        int cn = c + 1;
        bool pf = (cn < kc);
        uint32_t st = sb + (cn & 1) * STAGEB;
        int kk = cn * 64;

        uint32_t sAh = sb + (c & 1) * STAGEB;
        uint32_t sAl = sAh + ATILE;
        uint32_t sBh = sAh + 2*ATILE;
        uint32_t sBl = sBh + BTILE;
        #pragma unroll
        for (int ks = 0; ks < 4; ks++) {
            uint32_t ah[2][4], al[2][4], bh[4][4], bl[4][4];
            // --- half 1 ---
            #pragma unroll
            for (int mf = 0; mf < 2; mf++) {
                int kl = ks * 16 + krow_l;
                uint32_t mb = (uint32_t)(wm * 32 + mf * 16 + mcol_l) * 2;
                uint32_t off = (uint32_t)kl * 128 + (mb ^ ((kl & 7) << 4));
                LDSM_X4T(ah[mf][0], ah[mf][1], ah[mf][2], ah[mf][3], sAh + off);
            }
            #pragma unroll
            for (int nf2 = 0; nf2 < 4; nf2++) {
                uint32_t off = (uint32_t)(wn * 64 + nf2 * 16 + brow_l) * 128 + ks * 32 + bcol_l;
                LDSM_X4(bh[nf2][0], bh[nf2][1], bh[nf2][2], bh[nf2][3], sBh + SWZ128(off));
            }
            if (pf) {
                fill_tile_km_part(st,         Ab + (size_t)kk * MTOT,         tid, ks);
                fill_tile_km_part(st + ATILE, Ab + (size_t)(KSP + kk) * MTOT, tid, ks);
            }
            #pragma unroll
            for (int mf = 0; mf < 2; mf++)
                #pragma unroll
                for (int nf = 0; nf < 8; nf++) {
                    uint32_t* bhp = &bh[nf >> 1][(nf & 1) * 2];
                    MMA16816(acc[mf][nf], ah[mf], bhp[0], bhp[1]);
                }
            // --- half 2 ---
            #pragma unroll
            for (int mf = 0; mf < 2; mf++) {
                int kl = ks * 16 + krow_l;
                uint32_t mb = (uint32_t)(wm * 32 + mf * 16 + mcol_l) * 2;
                uint32_t off = (uint32_t)kl * 128 + (mb ^ ((kl & 7) << 4));
                LDSM_X4T(al[mf][0], al[mf][1], al[mf][2], al[mf][3], sAl + off);
            }
            #pragma unroll
            for (int nf2 = 0; nf2 < 4; nf2++) {
                uint32_t off = (uint32_t)(wn * 64 + nf2 * 16 + brow_l) * 128 + ks * 32 + bcol_l;
                LDSM_X4(bl[nf2][0], bl[nf2][1], bl[nf2][2], bl[nf2][3], sBl + SWZ128(off));
            }
            if (pf) {
                fill_tileB_part(st + 2*ATILE,         Bb + kk,       tid, ks);
                fill_tileB_part(st + 2*ATILE + BTILE, Bb + KSP + kk, tid, ks);
            }
            #pragma unroll
            for (int mf = 0; mf < 2; mf++)
                #pragma unroll
                for (int nf = 0; nf < 8; nf++) {
                    uint32_t* bhp = &bh[nf >> 1][(nf & 1) * 2];
                    uint32_t* blp = &bl[nf >> 1][(nf & 1) * 2];
                    MMA16816(acc[mf][nf], al[mf], bhp[0], bhp[1]);
                    MMA16816(acc[mf][nf], ah[mf], blp[0], blp[1]);
                }
        }
        asm volatile("cp.async.commit_group;");
    }

    #pragma unroll
    for (int mf = 0; mf < 2; mf++) {
        int m = m0 + wm * 32 + mf * 16 + gid;
        #pragma unroll
        for (int nf = 0; nf < 8; nf++) {
            int n = n0 + wn * 64 + nf * 8 + tg * 2;
            float2 v0 = make_float2(acc[mf][nf][0] + br[nf].x, acc[mf][nf][1] + br[nf].y);
            float2 v1 = make_float2(acc[mf][nf][2] + br[nf].x, acc[mf][nf][3] + br[nf].y);
            *reinterpret_cast<float2*>(C + (size_t)m * N + n) = v0;
            *reinterpret_cast<float2*>(C + (size_t)(m + 8) * N + n) = v1;
        }
    }
}

// ---------------- bf16 split prep kernels ----------------------------------
__global__ void splitA1_kernel(const float* __restrict__ u, __nv_bfloat16* __restrict__ Ac) {
    int m = blockIdx.y;
    int k4 = (blockIdx.x * 192 + threadIdx.x) * 4;
    float4 x = *reinterpret_cast<const float4*>(u + (size_t)m * D_ + k4);
    __nv_bfloat16 h0 = __float2bfloat16(x.x), h1 = __float2bfloat16(x.y);
    __nv_bfloat16 h2 = __float2bfloat16(x.z), h3 = __float2bfloat16(x.w);
    __nv_bfloat162 hi01, hi23, lo01, lo23;
    hi01.x = h0; hi01.y = h1; hi23.x = h2; hi23.y = h3;
    lo01.x = __float2bfloat16(x.x - __bfloat162float(h0));
    lo01.y = __float2bfloat16(x.y - __bfloat162float(h1));
    lo23.x = __float2bfloat16(x.z - __bfloat162float(h2));
    lo23.y = __float2bfloat16(x.w - __bfloat162float(h3));
    size_t base = (size_t)m * LDA + k4;
    *reinterpret_cast<__nv_bfloat162*>(&Ac[base])           = hi01;
    *reinterpret_cast<__nv_bfloat162*>(&Ac[base + 2])       = hi23;
    *reinterpret_cast<__nv_bfloat162*>(&Ac[base + KSP])     = lo01;
    *reinterpret_cast<__nv_bfloat162*>(&Ac[base + KSP + 2]) = lo23;
}

__global__ void splitB_kernel(const float* __restrict__ W, __nv_bfloat16* __restrict__ Bc,
                              int N) {
    __shared__ float t[32][33];
    int n0 = blockIdx.x * 32, k0 = blockIdx.y * 32;
    int tx = threadIdx.x, ty = threadIdx.y;
    for (int r = ty; r < 32; r += 8) t[r][tx] = W[(size_t)(k0 + r) * N + n0 + tx];
    __syncthreads();
    for (int r = ty; r < 32; r += 8) {
        float x = t[tx][r];
        __nv_bfloat16 hi = __float2bfloat16(x);
        float lo = x - __bfloat162float(hi);
        size_t base = (size_t)(n0 + r) * LDA + k0 + tx;
        Bc[base] = hi;
        Bc[base + KSP] = __float2bfloat16(lo);
    }
}

// ---------------- filter taps ------------------------------------------------
__global__ void h1_kernel(const float* __restrict__ W1, const float* __restrict__ b1) {
    int l = blockIdx.x;
    int f = threadIdx.x;
    __shared__ float spe[EMB_];
    float t = (float)l / (float)(L_ - 1);
    if (f < EMB_) spe[f] = sinf(t * (float)f * FREQ_);
    __syncthreads();
    float acc = b1[f];
    #pragma unroll
    for (int e = 0; e < EMB_; e++) acc += spe[e] * W1[e * FFN_ + f];
    g_h1[l * FFN_ + f] = sinf(FREQ_ * acc);
}

__global__ void taps_kernel(const float* __restrict__ W2, const float* __restrict__ b2,
                            const float* __restrict__ f_decay) {
    int idx = blockIdx.x * blockDim.x + threadIdx.x;
    if (idx >= 2 * D_ * TAPS) return;
    int c = idx / TAPS;
    int l = idx % TAPS;
    float acc = b2[c];
    #pragma unroll 8
    for (int f = 0; f < FFN_; f++) acc += g_h1[l * FFN_ + f] * W2[f * OD_ + c];
    float lam = expf(f_decay[c]);
    float tw = (float)l * ((float)L_ / (float)(L_ - 1));
    g_taps[c * TAPS + l] = acc * expf(-lam * tw);
}

// ---------------- fused: conv3 + (cumsum+FIR+gate) x 2 orders + bf16 split ---
__global__ void __launch_bounds__(256)
fir_kernel(const float* __restrict__ projT, const float* __restrict__ taps_all,
           const float* __restrict__ f_bias, const float* __restrict__ conv_k,
           const float* __restrict__ conv_b, __nv_bfloat16* __restrict__ A2T) {
    __shared__ __align__(16) float sv[TAPS + L_];
    __shared__ __align__(16) float sg[4 + L_];
    __shared__ float st[2 * TAPS];
    __shared__ float wsum[8];
    int ch = blockIdx.x;
    int b = ch / D_;
    int d = ch - b * D_;
    int tid = threadIdx.x;
    int lane = tid & 31;
    int warp = tid >> 5;
    int t0 = tid * 16;

    if (tid < TAPS) {
        sv[tid] = 0.0f;
        st[tid]        = taps_all[(size_t)d * TAPS + tid];
        st[TAPS + tid] = taps_all[(size_t)(D_ + d) * TAPS + tid];
    }
    if (tid < 4) sg[tid] = 0.0f;

    {
        const float* grow = projT + (size_t)d * MTOT + (size_t)b * L_;
        for (int i = tid; i < L_ / 4; i += 256)
            *reinterpret_cast<float4*>(&sg[4 + i * 4]) =
                *reinterpret_cast<const float4*>(&grow[i * 4]);
        const float* vrow = projT + (size_t)(2 * D_ + d) * MTOT + (size_t)b * L_;
        for (int i = tid; i < L_ / 4; i += 256)
            *reinterpret_cast<float4*>(&sv[TAPS + i * 4]) =
                *reinterpret_cast<const float4*>(&vrow[i * 4]);
        __syncthreads();
        float r[18];
        #pragma unroll
        for (int j = 0; j < 18; j++) r[j] = sv[TAPS + t0 - 2 + j];
        float vk0 = conv_k[2 * D_ + d], vk1 = conv_k[CD_ + 2 * D_ + d];
        float vk2 = conv_k[2 * CD_ + 2 * D_ + d], vcb = conv_b[2 * D_ + d];
        __syncthreads();
        #pragma unroll
        for (int j = 0; j < 16; j++)
            sv[TAPS + t0 + j] = r[j] * vk0 + r[j + 1] * vk1 + r[j + 2] * vk2 + vcb;
        __syncthreads();
    }

    float y[16];
    #pragma unroll
    for (int ord = 0; ord < 2; ord++) {
        float cs0 = 0.0f;
        #pragma unroll
        for (int j = 0; j < 16; j++) cs0 += sv[TAPS + t0 + j];
        float cs = cs0;
        #pragma unroll
        for (int o = 1; o < 32; o <<= 1) {
            float n = __shfl_up_sync(0xffffffffu, cs, o);
            if (lane >= o) cs += n;
        }
        if (lane == 31) wsum[warp] = cs;
        __syncthreads();
        if (warp == 0 && lane < 8) {
            float w = wsum[lane];
            #pragma unroll
            for (int o = 1; o < 8; o <<= 1) {
                float n = __shfl_up_sync(0xffu, w, o);
                if (lane >= o) w += n;
            }
            wsum[lane] = w;
        }
        __syncthreads();
        float pre = cs - cs0 + (warp > 0 ? wsum[warp - 1] : 0.0f);
        float fb = f_bias[ord * D_ + d];

        float acc[16];
        #pragma unroll
        for (int j = 0; j < 16; j++) {
            pre += sv[TAPS + t0 + j];
            acc[j] = fb * pre;
        }
        #pragma unroll
        for (int lc = 0; lc < TAPS / 16; lc++) {
            float tp[16];
            #pragma unroll
            for (int i = 0; i < 16; i++) tp[i] = st[ord * TAPS + lc * 16 + i];
            int base = TAPS + t0 - lc * 16 - 15;
            float w[31];
            #pragma unroll
            for (int m = 0; m < 31; m++) w[m] = sv[base + m];
            #pragma unroll
            for (int i = 0; i < 16; i++)
                #pragma unroll
                for (int j = 0; j < 16; j++)
                    acc[j] += tp[i] * w[15 - i + j];
        }

        float gk0 = conv_k[ord * D_ + d], gk1 = conv_k[CD_ + ord * D_ + d];
        float gk2 = conv_k[2 * CD_ + ord * D_ + d], gcb = conv_b[ord * D_ + d];
        float gr[18];
        #pragma unroll
        for (int j = 0; j < 18; j++) gr[j] = sg[2 + t0 + j];
        #pragma unroll
        for (int j = 0; j < 16; j++)
            y[j] = acc[j] * (gr[j] * gk0 + gr[j + 1] * gk1 + gr[j + 2] * gk2 + gcb);

        if (ord == 0) {
            __syncthreads();
            #pragma unroll
            for (int j = 0; j < 16; j++) sv[TAPS + t0 + j] = y[j];
            const float* grow = projT + (size_t)(D_ + d) * MTOT + (size_t)b * L_;
            for (int i = tid; i < L_ / 4; i += 256)
                *reinterpret_cast<float4*>(&sg[4 + i * 4]) =
                    *reinterpret_cast<const float4*>(&grow[i * 4]);
            __syncthreads();
        }
    }

    __nv_bfloat16* dhi = A2T + (size_t)d * MTOT + (size_t)b * L_ + t0;
    __nv_bfloat16* dlo = A2T + (size_t)(KSP + d) * MTOT + (size_t)b * L_ + t0;
    __nv_bfloat16 hi16[16], lo16[16];
    #pragma unroll
    for (int j = 0; j < 16; j++) {
        hi16[j] = __float2bfloat16(y[j]);
        lo16[j] = __float2bfloat16(y[j] - __bfloat162float(hi16[j]));
    }
    #pragma unroll
    for (int j = 0; j < 16; j += 8) {
        *reinterpret_cast<uint4*>(dhi + j) = *reinterpret_cast<uint4*>(&hi16[j]);
        *reinterpret_cast<uint4*>(dlo + j) = *reinterpret_cast<uint4*>(&lo16[j]);
    }
}

// ---------------- launch -------------------------------------------------------
extern "C" void kernel_launch(void* const* d_in, const int* in_sizes, int n_in,
                              void* d_out, int out_size) {
    const float* u       = (const float*)d_in[0];
    const float* W_in    = (const float*)d_in[1];
    const float* b_in    = (const float*)d_in[2];
    const float* conv_k  = (const float*)d_in[3];
    const float* conv_b  = (const float*)d_in[4];
    const float* W1      = (const float*)d_in[5];
    const float* b1      = (const float*)d_in[6];
    const float* W2      = (const float*)d_in[7];
    const float* b2      = (const float*)d_in[8];
    const float* f_bias  = (const float*)d_in[9];
    const float* f_decay = (const float*)d_in[10];
    const float* W_out   = (const float*)d_in[11];
    const float* b_out   = (const float*)d_in[12];
    float* out = (float*)d_out;

    float *projT, *tapsp;
    __nv_bfloat16 *A1, *B1, *A2T, *B2;
    cudaGetSymbolAddress((void**)&projT, g_projT);
    cudaGetSymbolAddress((void**)&tapsp, g_taps);
    cudaGetSymbolAddress((void**)&A1,  g_A1);
    cudaGetSymbolAddress((void**)&B1,  g_B1);
    cudaGetSymbolAddress((void**)&A2T, g_A2T);
    cudaGetSymbolAddress((void**)&B2,  g_B2);

    cudaFuncSetAttribute(gemm_hmma_kernel,  cudaFuncAttributeMaxDynamicSharedMemorySize, GSMEM);
    cudaFuncSetAttribute(gemm2_hmma_kernel, cudaFuncAttributeMaxDynamicSharedMemorySize, GSMEM);

    // launch order keeps gemm1 as launch #4 (ncu profiles it)
    splitA1_kernel<<<dim3(1, MTOT), 192>>>(u, A1);                               // 1
    splitB_kernel<<<dim3(CD_ / 32, D_ / 32), dim3(32, 8)>>>(W_in, B1, CD_);      // 2
    h1_kernel<<<TAPS, FFN_>>>(W1, b1);                                           // 3

    gemm_hmma_kernel<<<dim3(CD_ / GBN, MTOT / GBM), 128, GSMEM>>>(               // 4
        A1, B1, b_in, projT, CD_);

    taps_kernel<<<(2 * D_ * TAPS + 255) / 256, 256>>>(W2, b2, f_decay);          // 5

    fir_kernel<<<B_ * D_, 256>>>(projT, tapsp, f_bias, conv_k, conv_b, A2T);

    splitB_kernel<<<dim3(D_ / 32, D_ / 32), dim3(32, 8)>>>(W_out, B2, D_);

    gemm2_hmma_kernel<<<dim3(D_ / GBN, MTOT / GBM), 128, GSMEM>>>(
        A2T, B2, b_out, out, D_);
}

// round 15
// speedup vs baseline: 1.0273x; 1.0273x over previous
#include <cuda_runtime.h>
#include <cuda_bf16.h>
#include <cstdint>

#define B_  4
#define L_  4096
#define D_  768
#define CD_ 2304
#define OD_ 1536
#define EMB_ 33
#define FFN_ 64
#define FREQ_ 10.0f
#define TAPS 32
#define MTOT (B_*L_)        // 16384
#define KSP  768
#define LDA  1536           // 2*KSP (hi|lo)

// ---------------- scratch ------------------------------------------------
__device__ float g_projT[ (size_t)CD_*MTOT ];
__device__ float g_h1   [ TAPS*FFN_ ];
__device__ float g_taps [ 2*D_*TAPS ];
__device__ __nv_bfloat16 g_A1 [(size_t)MTOT*LDA];   // [m][2K]
__device__ __nv_bfloat16 g_B1 [(size_t)CD_*LDA];
__device__ __nv_bfloat16 g_A2T[(size_t)LDA*MTOT];   // [2K][m] K-major
__device__ __nv_bfloat16 g_B2 [(size_t)D_*LDA];

// ---------------- helpers --------------------------------------------------
__device__ __forceinline__ uint32_t smem_u32(const void* p) {
    uint32_t a;
    asm("{ .reg .u64 t; cvta.to.shared.u64 t, %1; cvt.u32.u64 %0, t; }" : "=r"(a) : "l"(p));
    return a;
}
#define SWZ128(o) ((o) ^ (((o) >> 3) & 0x70))

#define LDSM_X4(r0,r1,r2,r3,addr)                                              \
    asm volatile("ldmatrix.sync.aligned.m8n8.x4.shared.b16 {%0,%1,%2,%3}, [%4];" \
        : "=r"(r0), "=r"(r1), "=r"(r2), "=r"(r3) : "r"(addr))

#define LDSM_X4T(r0,r1,r2,r3,addr)                                             \
    asm volatile("ldmatrix.sync.aligned.m8n8.x4.trans.shared.b16 {%0,%1,%2,%3}, [%4];" \
        : "=r"(r0), "=r"(r1), "=r"(r2), "=r"(r3) : "r"(addr))

#define MMA16816(d, a, b0, b1)                                                 \
    asm volatile("mma.sync.aligned.m16n8k16.row.col.f32.bf16.bf16.f32 "        \
        "{%0,%1,%2,%3},{%4,%5,%6,%7},{%8,%9},{%0,%1,%2,%3};"                   \
        : "+f"((d)[0]), "+f"((d)[1]), "+f"((d)[2]), "+f"((d)[3])               \
        : "r"((a)[0]), "r"((a)[1]), "r"((a)[2]), "r"((a)[3]), "r"(b0), "r"(b1))

// 64(M) x 128(N) CTA tile, 128 threads, warp tile 32x64.
// Superchunk stage: A_hi | A_lo | B_hi | B_lo (hi/lo for the SAME 64 k's)
#define GBM 64
#define GBN 128
#define ATILE 8192
#define BTILE 16384
#define STAGEB (2*ATILE + 2*BTILE)   // 49152
#define NSTAGE 2
#define GSMEM (NSTAGE*STAGEB)        // 98304

// quarter-fills: issue 1/4 of a tile's cp.asyncs (part = 0..3)
__device__ __forceinline__ void fill_tileA_part(uint32_t sdst, const __nv_bfloat16* g,
                                                int tid, int part) {
    int idx = tid + (part << 7);
    int row = idx >> 3;
    int c16 = idx & 7;
    uint32_t bo = (uint32_t)(row << 7) + (c16 << 4);
    const void* src = g + (size_t)row * LDA + (c16 << 3);
    asm volatile("cp.async.cg.shared.global [%0], [%1], 16;"
                 :: "r"(sdst + SWZ128(bo)), "l"(src));
}

__device__ __forceinline__ void fill_tileB_part(uint32_t sdst, const __nv_bfloat16* g,
                                                int tid, int part) {
    #pragma unroll
    for (int j = 0; j < 2; j++) {
        int idx = tid + ((part * 2 + j) << 7);
        int row = idx >> 3;
        int c16 = idx & 7;
        uint32_t bo = (uint32_t)(row << 7) + (c16 << 4);
        const void* src = g + (size_t)row * LDA + (c16 << 3);
        asm volatile("cp.async.cg.shared.global [%0], [%1], 16;"
                     :: "r"(sdst + SWZ128(bo)), "l"(src));
    }
}

__device__ __forceinline__ void fill_tile_km_part(uint32_t sdst, const __nv_bfloat16* g,
                                                  int tid, int part) {
    int idx = tid + (part << 7);
    int k  = idx >> 3;
    int mc = idx & 7;
    uint32_t bo = (uint32_t)k * 128 + (((uint32_t)mc << 4) ^ ((k & 7) << 4));
    const void* src = g + (size_t)k * MTOT + (mc << 3);
    asm volatile("cp.async.cg.shared.global [%0], [%1], 16;"
                 :: "r"(sdst + bo), "l"(src));
}

__device__ __forceinline__ void fill_tileA(uint32_t sdst, const __nv_bfloat16* g, int tid) {
    #pragma unroll
    for (int p = 0; p < 4; p++) fill_tileA_part(sdst, g, tid, p);
}
__device__ __forceinline__ void fill_tileB(uint32_t sdst, const __nv_bfloat16* g, int tid) {
    #pragma unroll
    for (int p = 0; p < 4; p++) fill_tileB_part(sdst, g, tid, p);
}
__device__ __forceinline__ void fill_tile_km(uint32_t sdst, const __nv_bfloat16* g, int tid) {
    #pragma unroll
    for (int p = 0; p < 4; p++) fill_tile_km_part(sdst, g, tid, p);
}

// ---------------- GEMM1: A[m][2K] row-major, C_T[n][MTOT] transposed out ----
__global__ void __launch_bounds__(128, 2)
gemm_hmma_kernel(const __nv_bfloat16* __restrict__ A, const __nv_bfloat16* __restrict__ Bm,
                 const float* __restrict__ bias, float* __restrict__ C, int N) {
    extern __shared__ __align__(1024) char smem[];
    uint32_t sb = smem_u32(smem);
    int tid = threadIdx.x;
    int lane = tid & 31;
    int wid = tid >> 5;
    int wm = wid & 1;
    int wn = wid >> 1;
    int m0 = blockIdx.y * GBM;
    int n0 = blockIdx.x * GBN;
    const __nv_bfloat16* Ab = A + (size_t)m0 * LDA;
    const __nv_bfloat16* Bb = Bm + (size_t)n0 * LDA;

    int gid = lane >> 2, tg = lane & 3;
    int arow_l = (lane & 7) + ((lane >> 3) & 1) * 8;
    int acol_l = (lane >> 4) * 16;
    int brow_l = (lane & 7) + (lane >> 4) * 8;
    int bcol_l = ((lane >> 3) & 1) * 16;

    float acc[2][8][4] = {};
    const int kc = KSP / 64;

    {
        uint32_t st = sb;
        fill_tileA(st,             Ab,       tid);
        fill_tileA(st + ATILE,     Ab + KSP, tid);
        fill_tileB(st + 2*ATILE,         Bb,       tid);
        fill_tileB(st + 2*ATILE + BTILE, Bb + KSP, tid);
        asm volatile("cp.async.commit_group;");
    }

    for (int c = 0; c < kc; c++) {
        asm volatile("cp.async.wait_group %0;" :: "n"(0));
        __syncthreads();
        int cn = c + 1;
        bool pf = (cn < kc);
        uint32_t st = sb + (cn & 1) * STAGEB;
        int kk = cn * 64;

        uint32_t sAh = sb + (c & 1) * STAGEB;
        uint32_t sAl = sAh + ATILE;
        uint32_t sBh = sAh + 2*ATILE;
        uint32_t sBl = sBh + BTILE;
        #pragma unroll
        for (int ks = 0; ks < 4; ks++) {
            uint32_t ah[2][4], al[2][4], bh[4][4], bl[4][4];
            #pragma unroll
            for (int mf = 0; mf < 2; mf++) {
                uint32_t off = (uint32_t)(wm * 32 + mf * 16 + arow_l) * 128 + ks * 32 + acol_l;
                LDSM_X4(ah[mf][0], ah[mf][1], ah[mf][2], ah[mf][3], sAh + SWZ128(off));
                LDSM_X4(al[mf][0], al[mf][1], al[mf][2], al[mf][3], sAl + SWZ128(off));
            }
            #pragma unroll
            for (int nf2 = 0; nf2 < 4; nf2++) {
                uint32_t off = (uint32_t)(wn * 64 + nf2 * 16 + brow_l) * 128 + ks * 32 + bcol_l;
                LDSM_X4(bh[nf2][0], bh[nf2][1], bh[nf2][2], bh[nf2][3], sBh + SWZ128(off));
                LDSM_X4(bl[nf2][0], bl[nf2][1], bl[nf2][2], bl[nf2][3], sBl + SWZ128(off));
            }
            // compressed prefetch window: all 4 quarters issued during ks=0,1
            if (pf && ks < 2) {
                #pragma unroll
                for (int q = 0; q < 2; q++) {
                    int part = ks * 2 + q;
                    fill_tileA_part(st,             Ab + kk,       tid, part);
                    fill_tileA_part(st + ATILE,     Ab + KSP + kk, tid, part);
                    fill_tileB_part(st + 2*ATILE,         Bb + kk,       tid, part);
                    fill_tileB_part(st + 2*ATILE + BTILE, Bb + KSP + kk, tid, part);
                }
            }
            #pragma unroll
            for (int mf = 0; mf < 2; mf++)
                #pragma unroll
                for (int nf = 0; nf < 8; nf++) {
                    uint32_t* bhp = &bh[nf >> 1][(nf & 1) * 2];
                    uint32_t* blp = &bl[nf >> 1][(nf & 1) * 2];
                    MMA16816(acc[mf][nf], ah[mf], bhp[0], bhp[1]);
                    MMA16816(acc[mf][nf], al[mf], bhp[0], bhp[1]);
                    MMA16816(acc[mf][nf], ah[mf], blp[0], blp[1]);
                }
        }
        asm volatile("cp.async.commit_group;");
    }

    // transposed epilogue through smem: smt[64][129]
    __syncthreads();
    float* smt = reinterpret_cast<float*>(smem);
    #pragma unroll
    for (int mf = 0; mf < 2; mf++) {
        int mr = wm * 32 + mf * 16 + gid;
        #pragma unroll
        for (int nf = 0; nf < 8; nf++) {
            int nr = wn * 64 + nf * 8 + tg * 2;
            smt[mr * 129 + nr]           = acc[mf][nf][0];
            smt[mr * 129 + nr + 1]       = acc[mf][nf][1];
            smt[(mr + 8) * 129 + nr]     = acc[mf][nf][2];
            smt[(mr + 8) * 129 + nr + 1] = acc[mf][nf][3];
        }
    }
    __syncthreads();
    int nl = tid >> 4;
    int ms = (tid & 15) * 4;
    #pragma unroll
    for (int it = 0; it < 16; it++) {
        int n = it * 8 + nl;
        float bn = bias[n0 + n];
        float4 v;
        v.x = smt[(ms + 0) * 129 + n] + bn;
        v.y = smt[(ms + 1) * 129 + n] + bn;
        v.z = smt[(ms + 2) * 129 + n] + bn;
        v.w = smt[(ms + 3) * 129 + n] + bn;
        *reinterpret_cast<float4*>(C + (size_t)(n0 + n) * MTOT + m0 + ms) = v;
    }
}

// ---------------- GEMM2: A K-major A2T[2K][MTOT], C[m][n] row-major ---------
__global__ void __launch_bounds__(128, 2)
gemm2_hmma_kernel(const __nv_bfloat16* __restrict__ AT, const __nv_bfloat16* __restrict__ Bm,
                  const float* __restrict__ bias, float* __restrict__ C, int N) {
    extern __shared__ __align__(1024) char smem[];
    uint32_t sb = smem_u32(smem);
    int tid = threadIdx.x;
    int lane = tid & 31;
    int wid = tid >> 5;
    int wm = wid & 1;
    int wn = wid >> 1;
    int m0 = blockIdx.y * GBM;
    int n0 = blockIdx.x * GBN;
    const __nv_bfloat16* Ab = AT + m0;
    const __nv_bfloat16* Bb = Bm + (size_t)n0 * LDA;

    int gid = lane >> 2, tg = lane & 3;
    float2 br[8];
    #pragma unroll
    for (int nf = 0; nf < 8; nf++) {
        int n = n0 + wn * 64 + nf * 8 + tg * 2;
        br[nf] = *reinterpret_cast<const float2*>(bias + n);
    }

    int krow_l = (lane & 7) + ((lane >> 4) & 1) * 8;
    int mcol_l = ((lane >> 3) & 1) * 8;
    int brow_l = (lane & 7) + (lane >> 4) * 8;
    int bcol_l = ((lane >> 3) & 1) * 16;

    float acc[2][8][4] = {};
    const int kc = KSP / 64;

    {
        uint32_t st = sb;
        fill_tile_km(st,         Ab,                      tid);
        fill_tile_km(st + ATILE, Ab + (size_t)KSP * MTOT, tid);
        fill_tileB(st + 2*ATILE,         Bb,       tid);
        fill_tileB(st + 2*ATILE + BTILE, Bb + KSP, tid);
        asm volatile("cp.async.commit_group;");
    }

    for (int c = 0; c < kc; c++) {
        asm volatile("cp.async.wait_group %0;" :: "n"(0));
        __syncthreads();
        int cn = c + 1;
        bool pf = (cn < kc);
        uint32_t st = sb + (cn & 1) * STAGEB;
        int kk = cn * 64;

        uint32_t sAh = sb + (c & 1) * STAGEB;
        uint32_t sAl = sAh + ATILE;
        uint32_t sBh = sAh + 2*ATILE;
        uint32_t sBl = sBh + BTILE;
        #pragma unroll
        for (int ks = 0; ks < 4; ks++) {
            uint32_t ah[2][4], al[2][4], bh[4][4], bl[4][4];
            #pragma unroll
            for (int mf = 0; mf < 2; mf++) {
                int kl = ks * 16 + krow_l;
                uint32_t mb = (uint32_t)(wm * 32 + mf * 16 + mcol_l) * 2;
                uint32_t off = (uint32_t)kl * 128 + (mb ^ ((kl & 7) << 4));
                LDSM_X4T(ah[mf][0], ah[mf][1], ah[mf][2], ah[mf][3], sAh + off);
                LDSM_X4T(al[mf][0], al[mf][1], al[mf][2], al[mf][3], sAl + off);
            }
            #pragma unroll
            for (int nf2 = 0; nf2 < 4; nf2++) {
                uint32_t off = (uint32_t)(wn * 64 + nf2 * 16 + brow_l) * 128 + ks * 32 + bcol_l;
                LDSM_X4(bh[nf2][0], bh[nf2][1], bh[nf2][2], bh[nf2][3], sBh + SWZ128(off));
                LDSM_X4(bl[nf2][0], bl[nf2][1], bl[nf2][2], bl[nf2][3], sBl + SWZ128(off));
            }
            if (pf && ks < 2) {
                #pragma unroll
                for (int q = 0; q < 2; q++) {
                    int part = ks * 2 + q;
                    fill_tile_km_part(st,         Ab + (size_t)kk * MTOT,         tid, part);
                    fill_tile_km_part(st + ATILE, Ab + (size_t)(KSP + kk) * MTOT, tid, part);
                    fill_tileB_part(st + 2*ATILE,         Bb + kk,       tid, part);
                    fill_tileB_part(st + 2*ATILE + BTILE, Bb + KSP + kk, tid, part);
                }
            }
            #pragma unroll
            for (int mf = 0; mf < 2; mf++)
                #pragma unroll
                for (int nf = 0; nf < 8; nf++) {
                    uint32_t* bhp = &bh[nf >> 1][(nf & 1) * 2];
                    uint32_t* blp = &bl[nf >> 1][(nf & 1) * 2];
                    MMA16816(acc[mf][nf], ah[mf], bhp[0], bhp[1]);
                    MMA16816(acc[mf][nf], al[mf], bhp[0], bhp[1]);
                    MMA16816(acc[mf][nf], ah[mf], blp[0], blp[1]);
                }
        }
        asm volatile("cp.async.commit_group;");
    }

    #pragma unroll
    for (int mf = 0; mf < 2; mf++) {
        int m = m0 + wm * 32 + mf * 16 + gid;
        #pragma unroll
        for (int nf = 0; nf < 8; nf++) {
            int n = n0 + wn * 64 + nf * 8 + tg * 2;
            float2 v0 = make_float2(acc[mf][nf][0] + br[nf].x, acc[mf][nf][1] + br[nf].y);
            float2 v1 = make_float2(acc[mf][nf][2] + br[nf].x, acc[mf][nf][3] + br[nf].y);
            *reinterpret_cast<float2*>(C + (size_t)m * N + n) = v0;
            *reinterpret_cast<float2*>(C + (size_t)(m + 8) * N + n) = v1;
        }
    }
}

// ---------------- bf16 split prep kernels ----------------------------------
__global__ void splitA1_kernel(const float* __restrict__ u, __nv_bfloat16* __restrict__ Ac) {
    int m = blockIdx.y;
    int k4 = (blockIdx.x * 192 + threadIdx.x) * 4;
    float4 x = *reinterpret_cast<const float4*>(u + (size_t)m * D_ + k4);
    __nv_bfloat16 h0 = __float2bfloat16(x.x), h1 = __float2bfloat16(x.y);
    __nv_bfloat16 h2 = __float2bfloat16(x.z), h3 = __float2bfloat16(x.w);
    __nv_bfloat162 hi01, hi23, lo01, lo23;
    hi01.x = h0; hi01.y = h1; hi23.x = h2; hi23.y = h3;
    lo01.x = __float2bfloat16(x.x - __bfloat162float(h0));
    lo01.y = __float2bfloat16(x.y - __bfloat162float(h1));
    lo23.x = __float2bfloat16(x.z - __bfloat162float(h2));
    lo23.y = __float2bfloat16(x.w - __bfloat162float(h3));
    size_t base = (size_t)m * LDA + k4;
    *reinterpret_cast<__nv_bfloat162*>(&Ac[base])           = hi01;
    *reinterpret_cast<__nv_bfloat162*>(&Ac[base + 2])       = hi23;
    *reinterpret_cast<__nv_bfloat162*>(&Ac[base + KSP])     = lo01;
    *reinterpret_cast<__nv_bfloat162*>(&Ac[base + KSP + 2]) = lo23;
}

__global__ void splitB_kernel(const float* __restrict__ W, __nv_bfloat16* __restrict__ Bc,
                              int N) {
    __shared__ float t[32][33];
    int n0 = blockIdx.x * 32, k0 = blockIdx.y * 32;
    int tx = threadIdx.x, ty = threadIdx.y;
    for (int r = ty; r < 32; r += 8) t[r][tx] = W[(size_t)(k0 + r) * N + n0 + tx];
    __syncthreads();
    for (int r = ty; r < 32; r += 8) {
        float x = t[tx][r];
        __nv_bfloat16 hi = __float2bfloat16(x);
        float lo = x - __bfloat162float(hi);
        size_t base = (size_t)(n0 + r) * LDA + k0 + tx;
        Bc[base] = hi;
        Bc[base + KSP] = __float2bfloat16(lo);
    }
}

// ---------------- filter taps ------------------------------------------------
__global__ void h1_kernel(const float* __restrict__ W1, const float* __restrict__ b1) {
    int l = blockIdx.x;
    int f = threadIdx.x;
    __shared__ float spe[EMB_];
    float t = (float)l / (float)(L_ - 1);
    if (f < EMB_) spe[f] = sinf(t * (float)f * FREQ_);
    __syncthreads();
    float acc = b1[f];
    #pragma unroll
    for (int e = 0; e < EMB_; e++) acc += spe[e] * W1[e * FFN_ + f];
    g_h1[l * FFN_ + f] = sinf(FREQ_ * acc);
}

__global__ void taps_kernel(const float* __restrict__ W2, const float* __restrict__ b2,
                            const float* __restrict__ f_decay) {
    int idx = blockIdx.x * blockDim.x + threadIdx.x;
    if (idx >= 2 * D_ * TAPS) return;
    int c = idx / TAPS;
    int l = idx % TAPS;
    float acc = b2[c];
    #pragma unroll 8
    for (int f = 0; f < FFN_; f++) acc += g_h1[l * FFN_ + f] * W2[f * OD_ + c];
    float lam = expf(f_decay[c]);
    float tw = (float)l * ((float)L_ / (float)(L_ - 1));
    g_taps[c * TAPS + l] = acc * expf(-lam * tw);
}

// ---------------- fused: conv3 + (cumsum+FIR+gate) x 2 orders + bf16 split ---
__global__ void __launch_bounds__(256)
fir_kernel(const float* __restrict__ projT, const float* __restrict__ taps_all,
           const float* __restrict__ f_bias, const float* __restrict__ conv_k,
           const float* __restrict__ conv_b, __nv_bfloat16* __restrict__ A2T) {
    __shared__ __align__(16) float sv[TAPS + L_];
    __shared__ __align__(16) float sg0[4 + L_];
    __shared__ __align__(16) float sg1[4 + L_];
    __shared__ float st[2 * TAPS];
    __shared__ float wsum[8];
    int ch = blockIdx.x;
    int b = ch / D_;
    int d = ch - b * D_;
    int tid = threadIdx.x;
    int lane = tid & 31;
    int warp = tid >> 5;
    int t0 = tid * 16;

    if (tid < TAPS) {
        sv[tid] = 0.0f;
        st[tid]        = taps_all[(size_t)d * TAPS + tid];
        st[TAPS + tid] = taps_all[(size_t)(D_ + d) * TAPS + tid];
    }
    if (tid < 4) { sg0[tid] = 0.0f; sg1[tid] = 0.0f; }

    // preload both gate rows and the v row
    {
        const float* g0 = projT + (size_t)d * MTOT + (size_t)b * L_;
        const float* g1 = projT + (size_t)(D_ + d) * MTOT + (size_t)b * L_;
        const float* vr = projT + (size_t)(2 * D_ + d) * MTOT + (size_t)b * L_;
        for (int i = tid; i < L_ / 4; i += 256) {
            *reinterpret_cast<float4*>(&sg0[4 + i * 4]) =
                *reinterpret_cast<const float4*>(&g0[i * 4]);
            *reinterpret_cast<float4*>(&sg1[4 + i * 4]) =
                *reinterpret_cast<const float4*>(&g1[i * 4]);
            *reinterpret_cast<float4*>(&sv[TAPS + i * 4]) =
                *reinterpret_cast<const float4*>(&vr[i * 4]);
        }
        __syncthreads();
        float r[18];
        #pragma unroll
        for (int j = 0; j < 18; j++) r[j] = sv[TAPS + t0 - 2 + j];
        float vk0 = conv_k[2 * D_ + d], vk1 = conv_k[CD_ + 2 * D_ + d];
        float vk2 = conv_k[2 * CD_ + 2 * D_ + d], vcb = conv_b[2 * D_ + d];
        __syncthreads();
        #pragma unroll
        for (int j = 0; j < 16; j++)
            sv[TAPS + t0 + j] = r[j] * vk0 + r[j + 1] * vk1 + r[j + 2] * vk2 + vcb;
        __syncthreads();
    }

    float y[16];
    #pragma unroll
    for (int ord = 0; ord < 2; ord++) {
        float cs0 = 0.0f;
        #pragma unroll
        for (int j = 0; j < 16; j++) cs0 += sv[TAPS + t0 + j];
        float cs = cs0;
        #pragma unroll
        for (int o = 1; o < 32; o <<= 1) {
            float n = __shfl_up_sync(0xffffffffu, cs, o);
            if (lane >= o) cs += n;
        }
        if (lane == 31) wsum[warp] = cs;
        __syncthreads();
        if (warp == 0 && lane < 8) {
            float w = wsum[lane];
            #pragma unroll
            for (int o = 1; o < 8; o <<= 1) {
                float n = __shfl_up_sync(0xffu, w, o);
                if (lane >= o) w += n;
            }
            wsum[lane] = w;
        }
        __syncthreads();
        float pre = cs - cs0 + (warp > 0 ? wsum[warp - 1] : 0.0f);
        float fb = f_bias[ord * D_ + d];

        float acc[16];
        #pragma unroll
        for (int j = 0; j < 16; j++) {
            pre += sv[TAPS + t0 + j];
            acc[j] = fb * pre;
        }
        #pragma unroll
        for (int lc = 0; lc < TAPS / 16; lc++) {
            float tp[16];
            #pragma unroll
            for (int i = 0; i < 16; i++) tp[i] = st[ord * TAPS + lc * 16 + i];
            int base = TAPS + t0 - lc * 16 - 15;
            float w[31];
            #pragma unroll
            for (int m = 0; m < 31; m++) w[m] = sv[base + m];
            #pragma unroll
            for (int i = 0; i < 16; i++)
                #pragma unroll
                for (int j = 0; j < 16; j++)
                    acc[j] += tp[i] * w[15 - i + j];
        }

        const float* sg = (ord == 0) ? sg0 : sg1;
        float gk0 = conv_k[ord * D_ + d], gk1 = conv_k[CD_ + ord * D_ + d];
        float gk2 = conv_k[2 * CD_ + ord * D_ + d], gcb = conv_b[ord * D_ + d];
        float gr[18];
        #pragma unroll
        for (int j = 0; j < 18; j++) gr[j] = sg[2 + t0 + j];
        #pragma unroll
        for (int j = 0; j < 16; j++)
            y[j] = acc[j] * (gr[j] * gk0 + gr[j + 1] * gk1 + gr[j + 2] * gk2 + gcb);

        if (ord == 0) {
            __syncthreads();
            #pragma unroll
            for (int j = 0; j < 16; j++) sv[TAPS + t0 + j] = y[j];
            __syncthreads();
        }
    }

    __nv_bfloat16* dhi = A2T + (size_t)d * MTOT + (size_t)b * L_ + t0;
    __nv_bfloat16* dlo = A2T + (size_t)(KSP + d) * MTOT + (size_t)b * L_ + t0;
    __nv_bfloat16 hi16[16], lo16[16];
    #pragma unroll
    for (int j = 0; j < 16; j++) {
        hi16[j] = __float2bfloat16(y[j]);
        lo16[j] = __float2bfloat16(y[j] - __bfloat162float(hi16[j]));
    }
    #pragma unroll
    for (int j = 0; j < 16; j += 8) {
        *reinterpret_cast<uint4*>(dhi + j) = *reinterpret_cast<uint4*>(&hi16[j]);
        *reinterpret_cast<uint4*>(dlo + j) = *reinterpret_cast<uint4*>(&lo16[j]);
    }
}

// ---------------- launch -------------------------------------------------------
extern "C" void kernel_launch(void* const* d_in, const int* in_sizes, int n_in,
                              void* d_out, int out_size) {
    const float* u       = (const float*)d_in[0];
    const float* W_in    = (const float*)d_in[1];
    const float* b_in    = (const float*)d_in[2];
    const float* conv_k  = (const float*)d_in[3];
    const float* conv_b  = (const float*)d_in[4];
    const float* W1      = (const float*)d_in[5];
    const float* b1      = (const float*)d_in[6];
    const float* W2      = (const float*)d_in[7];
    const float* b2      = (const float*)d_in[8];
    const float* f_bias  = (const float*)d_in[9];
    const float* f_decay = (const float*)d_in[10];
    const float* W_out   = (const float*)d_in[11];
    const float* b_out   = (const float*)d_in[12];
    float* out = (float*)d_out;

    float *projT, *tapsp;
    __nv_bfloat16 *A1, *B1, *A2T, *B2;
    cudaGetSymbolAddress((void**)&projT, g_projT);
    cudaGetSymbolAddress((void**)&tapsp, g_taps);
    cudaGetSymbolAddress((void**)&A1,  g_A1);
    cudaGetSymbolAddress((void**)&B1,  g_B1);
    cudaGetSymbolAddress((void**)&A2T, g_A2T);
    cudaGetSymbolAddress((void**)&B2,  g_B2);

    cudaFuncSetAttribute(gemm_hmma_kernel,  cudaFuncAttributeMaxDynamicSharedMemorySize, GSMEM);
    cudaFuncSetAttribute(gemm2_hmma_kernel, cudaFuncAttributeMaxDynamicSharedMemorySize, GSMEM);

    // launch order keeps gemm1 as launch #4 (ncu profiles it)
    splitA1_kernel<<<dim3(1, MTOT), 192>>>(u, A1);                               // 1
    splitB_kernel<<<dim3(CD_ / 32, D_ / 32), dim3(32, 8)>>>(W_in, B1, CD_);      // 2
    h1_kernel<<<TAPS, FFN_>>>(W1, b1);                                           // 3

    gemm_hmma_kernel<<<dim3(CD_ / GBN, MTOT / GBM), 128, GSMEM>>>(               // 4
        A1, B1, b_in, projT, CD_);

    taps_kernel<<<(2 * D_ * TAPS + 255) / 256, 256>>>(W2, b2, f_decay);          // 5

    fir_kernel<<<B_ * D_, 256>>>(projT, tapsp, f_bias, conv_k, conv_b, A2T);

    splitB_kernel<<<dim3(D_ / 32, D_ / 32), dim3(32, 8)>>>(W_out, B2, D_);

    gemm2_hmma_kernel<<<dim3(D_ / GBN, MTOT / GBM), 128, GSMEM>>>(
        A2T, B2, b_out, out, D_);
}